// round 7
// baseline (speedup 1.0000x reference)
#include <cuda_runtime.h>
#include <math.h>

#define B 32
#define NN 128
#define C 128
#define HE 64
#define NH 256
#define OUT 10
#define EPS_BN 1e-5f

// ---------------- scratch (device globals; no allocs allowed) ----------------
__device__ float g_u[B*NN*HE];
__device__ float g_v[B*NN*HE];
__device__ float g_s[B*NN*NN];
__device__ float g_y[B*NN*NN];
__device__ float g_rs[B*NN];
__device__ float g_An[B*NN*NN];
__device__ float g_L0[B*NN*NN];
__device__ float g_L1[B*NN*NN];
__device__ float g_D[2*B*NN];
__device__ float g_Xcat[B*NN*1536];   // max 6*256 wide
__device__ float g_h0[B*NN*512];
__device__ float g_h1[B*NN*512];
__device__ float g_pool[B*512];
__device__ float g_fc1[B*NH];

__device__ __forceinline__ unsigned f2tf(float f) {
    unsigned u;
    asm("cvt.rna.tf32.f32 %0, %1;" : "=r"(u) : "f"(f));
    return u;
}

__device__ __forceinline__ void mma_tf32(float c[4], const unsigned a[4], const unsigned b[2]) {
    asm volatile(
        "mma.sync.aligned.m16n8k8.row.col.f32.tf32.tf32.f32 "
        "{%0,%1,%2,%3}, {%4,%5,%6,%7}, {%8,%9}, {%0,%1,%2,%3};"
        : "+f"(c[0]), "+f"(c[1]), "+f"(c[2]), "+f"(c[3])
        : "r"(a[0]), "r"(a[1]), "r"(a[2]), "r"(a[3]), "r"(b[0]), "r"(b[1]));
}

// ---------------- edge MLP: u = x@eW1[:C]+eb1, v = x@eW1[C:] ----------------
__global__ void k_uv(const float* __restrict__ x, const float* __restrict__ eW1,
                     const float* __restrict__ eb1) {
    int row = blockIdx.x;            // b*NN + n
    __shared__ float xs[C];
    for (int c = threadIdx.x; c < C; c += blockDim.x) xs[c] = x[row*C + c];
    __syncthreads();
    int t = threadIdx.x;             // 64 threads = HE
    float u = 0.f, v = 0.f;
#pragma unroll 4
    for (int c = 0; c < C; c++) {
        float xv = xs[c];
        u += xv * eW1[c*HE + t];
        v += xv * eW1[(C + c)*HE + t];
    }
    g_u[row*HE + t] = u + eb1[t];
    g_v[row*HE + t] = v;
}

// ---------------- edge scores s[b,i,j] ----------------
#define IC 16
__global__ void k_score(const float* __restrict__ eW2, const float* __restrict__ eb2) {
    int b  = blockIdx.x / (NN / IC);
    int i0 = (blockIdx.x % (NN / IC)) * IC;
    __shared__ float vs[NN*(HE + 1)];
    __shared__ float us[IC*HE];
    __shared__ float w2[HE];
    int tid = threadIdx.x;           // 128
    for (int idx = tid; idx < NN*HE; idx += 128) {
        int j = idx / HE, h = idx % HE;
        vs[j*(HE + 1) + h] = g_v[(b*NN + j)*HE + h];
    }
    for (int idx = tid; idx < IC*HE; idx += 128)
        us[idx] = g_u[(b*NN + i0)*HE + idx];
    if (tid < HE) w2[tid] = eW2[tid];
    __syncthreads();
    float e2 = eb2[0];
    int j = tid;
    for (int ii = 0; ii < IC; ii++) {
        float acc = e2;
#pragma unroll 8
        for (int h = 0; h < HE; h++) {
            float t = us[ii*HE + h] + vs[j*(HE + 1) + h];
            acc += w2[h] * fmaxf(t, 0.f);
        }
        g_s[(b*NN + i0 + ii)*NN + j] = acc;
    }
}

// ---------------- y = exp(.5(s+s^T)) * triu * mask ; row sums ----------------
__global__ void k_y(const float* __restrict__ mask) {
    int b = blockIdx.x / NN, i = blockIdx.x % NN;
    int j = threadIdx.x;
    float val = 0.f;
    if (i < j) {
        float m = mask[b*NN + i] * mask[b*NN + j];
        if (m != 0.f)
            val = expf(0.5f * (g_s[(b*NN + i)*NN + j] + g_s[(b*NN + j)*NN + i]));
    }
    g_y[(b*NN + i)*NN + j] = val;
    __shared__ float red[4];
    float s = val;
    for (int o = 16; o; o >>= 1) s += __shfl_down_sync(0xffffffffu, s, o);
    if ((j & 31) == 0) red[j >> 5] = s;
    __syncthreads();
    if (j == 0) {
        float tot = red[0] + red[1] + red[2] + red[3];
        g_rs[b*NN + i] = (tot == 0.f) ? 1.f : tot;
    }
}

// ---------------- An = y/rs + (y/rs)^T ----------------
__global__ void k_an() {
    for (int idx = blockIdx.x*blockDim.x + threadIdx.x; idx < B*NN*NN;
         idx += gridDim.x*blockDim.x) {
        int b = idx / (NN*NN);
        int r = (idx / NN) % NN;
        int c = idx % NN;
        g_An[idx] = g_y[idx] / g_rs[b*NN + r]
                  + g_y[(b*NN + c)*NN + r] / g_rs[b*NN + c];
    }
}

// ---------------- D[b,j] = rsqrt(colsum + 1e-5) ----------------
__global__ void k_D(const float* __restrict__ Amat, float* __restrict__ Dout) {
    int b = blockIdx.x, j = threadIdx.x;
    float s = 0.f;
#pragma unroll 4
    for (int i = 0; i < NN; i++) s += Amat[(b*NN + i)*NN + j];
    Dout[b*NN + j] = rsqrtf(s + 1e-5f);
}

// ---------------- L = D_i * A * D_j ----------------
__global__ void k_L(const float* __restrict__ Amat, const float* __restrict__ D,
                    float* __restrict__ Lout) {
    for (int idx = blockIdx.x*blockDim.x + threadIdx.x; idx < B*NN*NN;
         idx += gridDim.x*blockDim.x) {
        int b = idx / (NN*NN);
        int r = (idx / NN) % NN;
        int c = idx % NN;
        Lout[idx] = D[b*NN + r] * Amat[idx] * D[b*NN + c];
    }
}

// ---------------- copy X into concat slots 0 and 3 ----------------
__global__ void k_copyX(const float* __restrict__ X, int fin) {
    int total = B*NN*fin;
    int w = 6*fin;
    for (int idx = blockIdx.x*blockDim.x + threadIdx.x; idx < total;
         idx += gridDim.x*blockDim.x) {
        int row = idx / fin, c = idx % fin;
        float v = X[idx];
        g_Xcat[row*w + c]           = v;
        g_Xcat[row*w + 3*fin + c]   = v;
    }
}

// =============== TF32 tensor-core batched GEMM ==================
// C[b](128 x 64tile) = alpha * L[b](128x128) @ Bm[b](128 x Nsub) (- Sub)
__global__ __launch_bounds__(256) void k_bgemm(
        const float* __restrict__ Lbase, const float* __restrict__ Bbase,
        int ldb, int colOffB,
        float* __restrict__ Cbase, int ldc, int colOffC,
        const float* __restrict__ Sub, int ldsub, int colOffSub,
        float alpha) {
    __shared__ unsigned As[128][36];
    __shared__ unsigned Bs[32][68];
    int b = blockIdx.z;
    int bcol = blockIdx.x * 64;
    const float* Lm = Lbase + (size_t)b*NN*NN;
    const float* Bm = Bbase + (size_t)b*NN*ldb + colOffB;
    float*       Cm = Cbase + (size_t)b*NN*ldc + colOffC;
    int t = threadIdx.x;
    int warp = t >> 5, lane = t & 31;
    int warpM = (warp >> 1) * 32, warpN = (warp & 1) * 32;
    int g = lane >> 2, tg = lane & 3;
    float acc[2][4][4] = {};
    for (int k0 = 0; k0 < NN; k0 += 32) {
#pragma unroll
        for (int r = 0; r < 4; r++) {
            int m = (t >> 3) + r*32;
            int kg = (t & 7) * 4;
            float4 v = *(const float4*)(Lm + (size_t)m*NN + k0 + kg);
            uint4 s; s.x = f2tf(v.x); s.y = f2tf(v.y); s.z = f2tf(v.z); s.w = f2tf(v.w);
            *(uint4*)&As[m][kg] = s;
        }
#pragma unroll
        for (int r = 0; r < 2; r++) {
            int kk = (t >> 4) + r*16;
            int nc = (t & 15) * 4;
            float4 v = *(const float4*)(Bm + (size_t)(k0 + kk)*ldb + bcol + nc);
            uint4 s; s.x = f2tf(v.x); s.y = f2tf(v.y); s.z = f2tf(v.z); s.w = f2tf(v.w);
            *(uint4*)&Bs[kk][nc] = s;
        }
        __syncthreads();
#pragma unroll
        for (int ks = 0; ks < 4; ks++) {
            int kb = ks * 8;
            unsigned a[2][4], bb[4][2];
#pragma unroll
            for (int mt = 0; mt < 2; mt++) {
                int r0 = warpM + mt*16 + g;
                a[mt][0] = As[r0][kb + tg];
                a[mt][1] = As[r0 + 8][kb + tg];
                a[mt][2] = As[r0][kb + tg + 4];
                a[mt][3] = As[r0 + 8][kb + tg + 4];
            }
#pragma unroll
            for (int nt = 0; nt < 4; nt++) {
                int c0 = warpN + nt*8 + g;
                bb[nt][0] = Bs[kb + tg][c0];
                bb[nt][1] = Bs[kb + tg + 4][c0];
            }
#pragma unroll
            for (int mt = 0; mt < 2; mt++)
#pragma unroll
                for (int nt = 0; nt < 4; nt++)
                    mma_tf32(acc[mt][nt], a[mt], bb[nt]);
        }
        __syncthreads();
    }
    const float* Sm = Sub ? (Sub + (size_t)b*NN*ldsub + colOffSub) : nullptr;
#pragma unroll
    for (int nt = 0; nt < 4; nt++) {
        int c0 = bcol + warpN + nt*8 + tg*2;
#pragma unroll
        for (int mt = 0; mt < 2; mt++) {
            int r0 = warpM + mt*16 + g;
            float v00 = alpha * acc[mt][nt][0];
            float v01 = alpha * acc[mt][nt][1];
            float v10 = alpha * acc[mt][nt][2];
            float v11 = alpha * acc[mt][nt][3];
            if (Sm) {
                v00 -= Sm[(size_t)r0*ldsub + c0];
                v01 -= Sm[(size_t)r0*ldsub + c0 + 1];
                v10 -= Sm[(size_t)(r0 + 8)*ldsub + c0];
                v11 -= Sm[(size_t)(r0 + 8)*ldsub + c0 + 1];
            }
            Cm[(size_t)r0*ldc + c0]         = v00;
            Cm[(size_t)r0*ldc + c0 + 1]     = v01;
            Cm[(size_t)(r0 + 8)*ldc + c0]     = v10;
            Cm[(size_t)(r0 + 8)*ldc + c0 + 1] = v11;
        }
    }
}

// ===== TF32 FC GEMM: O = relu(BN(mask * (Xcat @ W + bias))) ; M=4096 =====
__global__ __launch_bounds__(256) void k_fcgemm(
        const float* __restrict__ X, const float* __restrict__ W,
        const float* __restrict__ bias, const float* __restrict__ bnm,
        const float* __restrict__ bnv, const float* __restrict__ bng,
        const float* __restrict__ bnb, const float* __restrict__ mask,
        float* __restrict__ O, int K, int Nc) {
    __shared__ unsigned As[128][36];
    __shared__ unsigned Bs[32][68];
    int brow = blockIdx.y * 128;
    int bcol = blockIdx.x * 64;
    int t = threadIdx.x;
    int warp = t >> 5, lane = t & 31;
    int warpM = (warp >> 1) * 32, warpN = (warp & 1) * 32;
    int g = lane >> 2, tg = lane & 3;
    float acc[2][4][4] = {};
    for (int k0 = 0; k0 < K; k0 += 32) {
#pragma unroll
        for (int r = 0; r < 4; r++) {
            int m = (t >> 3) + r*32;
            int kg = (t & 7) * 4;
            float4 v = *(const float4*)(X + (size_t)(brow + m)*K + k0 + kg);
            uint4 s; s.x = f2tf(v.x); s.y = f2tf(v.y); s.z = f2tf(v.z); s.w = f2tf(v.w);
            *(uint4*)&As[m][kg] = s;
        }
#pragma unroll
        for (int r = 0; r < 2; r++) {
            int kk = (t >> 4) + r*16;
            int nc = (t & 15) * 4;
            float4 v = *(const float4*)(W + (size_t)(k0 + kk)*Nc + bcol + nc);
            uint4 s; s.x = f2tf(v.x); s.y = f2tf(v.y); s.z = f2tf(v.z); s.w = f2tf(v.w);
            *(uint4*)&Bs[kk][nc] = s;
        }
        __syncthreads();
#pragma unroll
        for (int ks = 0; ks < 4; ks++) {
            int kb = ks * 8;
            unsigned a[2][4], bb[4][2];
#pragma unroll
            for (int mt = 0; mt < 2; mt++) {
                int r0 = warpM + mt*16 + g;
                a[mt][0] = As[r0][kb + tg];
                a[mt][1] = As[r0 + 8][kb + tg];
                a[mt][2] = As[r0][kb + tg + 4];
                a[mt][3] = As[r0 + 8][kb + tg + 4];
            }
#pragma unroll
            for (int nt = 0; nt < 4; nt++) {
                int c0 = warpN + nt*8 + g;
                bb[nt][0] = Bs[kb + tg][c0];
                bb[nt][1] = Bs[kb + tg + 4][c0];
            }
#pragma unroll
            for (int mt = 0; mt < 2; mt++)
#pragma unroll
                for (int nt = 0; nt < 4; nt++)
                    mma_tf32(acc[mt][nt], a[mt], bb[nt]);
        }
        __syncthreads();
    }
#pragma unroll
    for (int nt = 0; nt < 4; nt++) {
        int c0 = bcol + warpN + nt*8 + tg*2;
        float sc0 = bng[c0]     * rsqrtf(bnv[c0]     + EPS_BN);
        float sc1 = bng[c0 + 1] * rsqrtf(bnv[c0 + 1] + EPS_BN);
        float bi0 = bias[c0], bi1 = bias[c0 + 1];
        float m0 = bnm[c0], m1 = bnm[c0 + 1];
        float be0 = bnb[c0], be1 = bnb[c0 + 1];
#pragma unroll
        for (int mt = 0; mt < 2; mt++) {
            int r0 = brow + warpM + mt*16 + g;
            float mk0 = mask[r0], mk1 = mask[r0 + 8];
            float v;
            v = ((acc[mt][nt][0] + bi0)*mk0 - m0)*sc0 + be0;
            O[(size_t)r0*Nc + c0]         = fmaxf(v, 0.f);
            v = ((acc[mt][nt][1] + bi1)*mk0 - m1)*sc1 + be1;
            O[(size_t)r0*Nc + c0 + 1]     = fmaxf(v, 0.f);
            v = ((acc[mt][nt][2] + bi0)*mk1 - m0)*sc0 + be0;
            O[(size_t)(r0 + 8)*Nc + c0]     = fmaxf(v, 0.f);
            v = ((acc[mt][nt][3] + bi1)*mk1 - m1)*sc1 + be1;
            O[(size_t)(r0 + 8)*Nc + c0 + 1] = fmaxf(v, 0.f);
        }
    }
}

// ---------------- max-pool over nodes ----------------
__global__ void k_pool(const float* __restrict__ H) {
    int b = blockIdx.x, c = threadIdx.x;      // 512
    float mx = H[(size_t)(b*NN)*512 + c];
    for (int n = 1; n < NN; n++)
        mx = fmaxf(mx, H[(size_t)(b*NN + n)*512 + c]);
    g_pool[b*512 + c] = mx;
}

// ---------------- classifier ----------------
__global__ void k_fc1(const float* __restrict__ fW1, const float* __restrict__ fb1) {
    int b = blockIdx.x, t = threadIdx.x;      // 256
    __shared__ float ps[512];
    for (int i = t; i < 512; i += 256) ps[i] = g_pool[b*512 + i];
    __syncthreads();
    float acc = fb1[t];
#pragma unroll 4
    for (int k = 0; k < 512; k++) acc += ps[k] * fW1[k*NH + t];
    g_fc1[b*NH + t] = acc;
}

__global__ void k_fc2(const float* __restrict__ fW2, const float* __restrict__ fb2,
                      float* __restrict__ out) {
    int b = blockIdx.x, t = threadIdx.x;      // 32
    __shared__ float ps[NH];
    for (int i = t; i < NH; i += 32) ps[i] = g_fc1[b*NH + i];
    __syncthreads();
    if (t < OUT) {
        float acc = fb2[t];
#pragma unroll 4
        for (int k = 0; k < NH; k++) acc += ps[k] * fW2[k*OUT + t];
        out[b*OUT + t] = acc;
    }
}

// ---------------- host launch ----------------
static void* dev_ptr(const void* sym) {
    void* p = nullptr;
    cudaGetSymbolAddress(&p, sym);
    return p;
}

extern "C" void kernel_launch(void* const* d_in, const int* in_sizes, int n_in,
                              void* d_out, int out_size) {
    const float* x    = (const float*)d_in[0];
    const float* A    = (const float*)d_in[1];
    const float* mask = (const float*)d_in[2];
    const float* eW1  = (const float*)d_in[3];
    const float* eb1  = (const float*)d_in[4];
    const float* eW2  = (const float*)d_in[5];
    const float* eb2  = (const float*)d_in[6];
    const float* gW[3]  = {(const float*)d_in[7],  (const float*)d_in[13], (const float*)d_in[19]};
    const float* gb[3]  = {(const float*)d_in[8],  (const float*)d_in[14], (const float*)d_in[20]};
    const float* bng[3] = {(const float*)d_in[9],  (const float*)d_in[15], (const float*)d_in[21]};
    const float* bnb[3] = {(const float*)d_in[10], (const float*)d_in[16], (const float*)d_in[22]};
    const float* bnm[3] = {(const float*)d_in[11], (const float*)d_in[17], (const float*)d_in[23]};
    const float* bnv[3] = {(const float*)d_in[12], (const float*)d_in[18], (const float*)d_in[24]};
    const float* fW1 = (const float*)d_in[25];
    const float* fb1 = (const float*)d_in[26];
    const float* fW2 = (const float*)d_in[27];
    const float* fb2 = (const float*)d_in[28];
    float* out = (float*)d_out;

    float* p_An   = (float*)dev_ptr(g_An);
    float* p_L0   = (float*)dev_ptr(g_L0);
    float* p_L1   = (float*)dev_ptr(g_L1);
    float* p_D    = (float*)dev_ptr(g_D);
    float* p_Xcat = (float*)dev_ptr(g_Xcat);
    float* p_h0   = (float*)dev_ptr(g_h0);
    float* p_h1   = (float*)dev_ptr(g_h1);

    // edge adjacency
    k_uv<<<B*NN, HE>>>(x, eW1, eb1);
    k_score<<<B*(NN/IC), 128>>>(eW2, eb2);
    k_y<<<B*NN, NN>>>(mask);
    k_an<<<512, 256>>>();

    // Laplacians (shared by all 3 layers)
    k_D<<<B, NN>>>(A, p_D);
    k_D<<<B, NN>>>(p_An, p_D + B*NN);
    k_L<<<512, 256>>>(A,    p_D,        p_L0);
    k_L<<<512, 256>>>(p_An, p_D + B*NN, p_L1);

    const int   FIN[3]  = {128, 64, 256};
    const int   FOUT[3] = {64, 256, 512};
    const float* Xin[3] = {x, p_h0, p_h1};
    float*      Hout[3] = {p_h0, p_h1, p_h0};

    for (int li = 0; li < 3; li++) {
        int fin = FIN[li], f = FOUT[li], w = 6*fin;
        int total = B*NN*fin;
        k_copyX<<<(total + 255)/256, 256>>>(Xin[li], fin);
        dim3 gb_(fin/64, 1, B);
        // T1 = L @ X
        k_bgemm<<<gb_, 256>>>(p_L0, Xin[li], fin, 0, p_Xcat, w, 1*fin, nullptr, 0, 0, 1.f);
        k_bgemm<<<gb_, 256>>>(p_L1, Xin[li], fin, 0, p_Xcat, w, 4*fin, nullptr, 0, 0, 1.f);
        // T2 = 2*L @ T1 - X
        k_bgemm<<<gb_, 256>>>(p_L0, p_Xcat, w, 1*fin, p_Xcat, w, 2*fin, Xin[li], fin, 0, 2.f);
        k_bgemm<<<gb_, 256>>>(p_L1, p_Xcat, w, 4*fin, p_Xcat, w, 5*fin, Xin[li], fin, 0, 2.f);
        // FC + mask + BN + relu
        dim3 gf(f/64, (B*NN)/128);
        k_fcgemm<<<gf, 256>>>(p_Xcat, gW[li], gb[li], bnm[li], bnv[li],
                              bng[li], bnb[li], mask, Hout[li], w, f);
    }

    k_pool<<<B, 512>>>(p_h0);
    k_fc1<<<B, NH>>>(fW1, fb1);
    k_fc2<<<B, 32>>>(fW2, fb2, out);
}

// round 9
// speedup vs baseline: 1.2656x; 1.2656x over previous
#include <cuda_runtime.h>
#include <math.h>

#define B 32
#define NN 128
#define C 128
#define HE 64
#define NH 256
#define OUT 10
#define EPS_BN 1e-5f

// ---------------- scratch (device globals; no allocs allowed) ----------------
__device__ float g_u[B*NN*HE];
__device__ float g_v[B*NN*HE];
__device__ float g_s[B*NN*NN];
__device__ float g_y[B*NN*NN];
__device__ float g_rs[B*NN];
__device__ float g_An[B*NN*NN];
__device__ float g_L0[B*NN*NN];
__device__ float g_L1[B*NN*NN];
__device__ float g_M0[B*NN*NN];
__device__ float g_M1[B*NN*NN];
__device__ float g_D[2*B*NN];
__device__ float g_Xcat[B*NN*1536];   // max 6*256 wide
__device__ float g_h0[B*NN*512];
__device__ float g_h1[B*NN*512];
__device__ float g_pool[B*512];
__device__ float g_fc1[B*NH];

__device__ __forceinline__ unsigned f2tf(float f) {
    unsigned u;
    asm("cvt.rna.tf32.f32 %0, %1;" : "=r"(u) : "f"(f));
    return u;
}
__device__ __forceinline__ uint4 f2tf4(float4 v) {
    uint4 s; s.x = f2tf(v.x); s.y = f2tf(v.y); s.z = f2tf(v.z); s.w = f2tf(v.w);
    return s;
}

__device__ __forceinline__ void mma_tf32(float c[4], const unsigned a[4], const unsigned b[2]) {
    asm volatile(
        "mma.sync.aligned.m16n8k8.row.col.f32.tf32.tf32.f32 "
        "{%0,%1,%2,%3}, {%4,%5,%6,%7}, {%8,%9}, {%0,%1,%2,%3};"
        : "+f"(c[0]), "+f"(c[1]), "+f"(c[2]), "+f"(c[3])
        : "r"(a[0]), "r"(a[1]), "r"(a[2]), "r"(a[3]), "r"(b[0]), "r"(b[1]));
}

// ---------------- edge MLP: u = x@eW1[:C]+eb1, v = x@eW1[C:] ----------------
__global__ void k_uv(const float* __restrict__ x, const float* __restrict__ eW1,
                     const float* __restrict__ eb1) {
    int row = blockIdx.x;            // b*NN + n
    __shared__ float xs[C];
    for (int c = threadIdx.x; c < C; c += blockDim.x) xs[c] = x[row*C + c];
    __syncthreads();
    int t = threadIdx.x;             // 64 threads = HE
    float u = 0.f, v = 0.f;
#pragma unroll 4
    for (int c = 0; c < C; c++) {
        float xv = xs[c];
        u += xv * eW1[c*HE + t];
        v += xv * eW1[(C + c)*HE + t];
    }
    g_u[row*HE + t] = u + eb1[t];
    g_v[row*HE + t] = v;
}

// ---------------- edge scores s[b,i,j] ----------------
#define IC 16
__global__ void k_score(const float* __restrict__ eW2, const float* __restrict__ eb2) {
    int b  = blockIdx.x / (NN / IC);
    int i0 = (blockIdx.x % (NN / IC)) * IC;
    __shared__ float vs[NN*(HE + 1)];
    __shared__ float us[IC*HE];
    __shared__ float w2[HE];
    int tid = threadIdx.x;           // 128
    for (int idx = tid; idx < NN*HE; idx += 128) {
        int j = idx / HE, h = idx % HE;
        vs[j*(HE + 1) + h] = g_v[(b*NN + j)*HE + h];
    }
    for (int idx = tid; idx < IC*HE; idx += 128)
        us[idx] = g_u[(b*NN + i0)*HE + idx];
    if (tid < HE) w2[tid] = eW2[tid];
    __syncthreads();
    float e2 = eb2[0];
    int j = tid;
    for (int ii = 0; ii < IC; ii++) {
        float acc = e2;
#pragma unroll 8
        for (int h = 0; h < HE; h++) {
            float t = us[ii*HE + h] + vs[j*(HE + 1) + h];
            acc += w2[h] * fmaxf(t, 0.f);
        }
        g_s[(b*NN + i0 + ii)*NN + j] = acc;
    }
}

// ---------------- y = exp(.5(s+s^T)) * triu * mask ; row sums ----------------
__global__ void k_y(const float* __restrict__ mask) {
    int b = blockIdx.x / NN, i = blockIdx.x % NN;
    int j = threadIdx.x;
    float val = 0.f;
    if (i < j) {
        float m = mask[b*NN + i] * mask[b*NN + j];
        if (m != 0.f)
            val = expf(0.5f * (g_s[(b*NN + i)*NN + j] + g_s[(b*NN + j)*NN + i]));
    }
    g_y[(b*NN + i)*NN + j] = val;
    __shared__ float red[4];
    float s = val;
    for (int o = 16; o; o >>= 1) s += __shfl_down_sync(0xffffffffu, s, o);
    if ((j & 31) == 0) red[j >> 5] = s;
    __syncthreads();
    if (j == 0) {
        float tot = red[0] + red[1] + red[2] + red[3];
        g_rs[b*NN + i] = (tot == 0.f) ? 1.f : tot;
    }
}

// ---------------- An = y/rs + (y/rs)^T ----------------
__global__ void k_an() {
    for (int idx = blockIdx.x*blockDim.x + threadIdx.x; idx < B*NN*NN;
         idx += gridDim.x*blockDim.x) {
        int b = idx / (NN*NN);
        int r = (idx / NN) % NN;
        int c = idx % NN;
        g_An[idx] = g_y[idx] / g_rs[b*NN + r]
                  + g_y[(b*NN + c)*NN + r] / g_rs[b*NN + c];
    }
}

// ---------------- D[b,j] = rsqrt(colsum + 1e-5) (both relations) ------------
__global__ void k_D2(const float* __restrict__ A) {
    int v = blockIdx.x;              // 0..2B-1
    int b = v % B;
    const float* Am = (v < B ? A + (size_t)b*NN*NN : g_An + (size_t)b*NN*NN);
    int j = threadIdx.x;
    float s = 0.f;
#pragma unroll 4
    for (int i = 0; i < NN; i++) s += Am[i*NN + j];
    g_D[v*NN + j] = rsqrtf(s + 1e-5f);
}

// ---------------- L = D_i * A * D_j (both relations) ----------------
__global__ void k_L2(const float* __restrict__ A) {
    int half = B*NN*NN;
    for (int idx = blockIdx.x*blockDim.x + threadIdx.x; idx < 2*half;
         idx += gridDim.x*blockDim.x) {
        int rel = idx / half;
        int l = idx - rel*half;
        int b = l / (NN*NN);
        int r = (l / NN) % NN;
        int c = l % NN;
        const float* Am = rel ? g_An : A;
        float* Lm = rel ? g_L1 : g_L0;
        const float* Dm = g_D + rel*B*NN;
        Lm[l] = Dm[b*NN + r] * Am[l] * Dm[b*NN + c];
    }
}

// =============== M = 2*L@L - I  (tf32 MMA, 128x64 tile, reg prefetch) =======
__global__ __launch_bounds__(256) void k_mgemm() {
    __shared__ unsigned As[128][36];
    __shared__ unsigned Bs[32][68];
    int rel = blockIdx.y, b = blockIdx.z, bcol = blockIdx.x * 64;
    const float* Lm = (rel ? g_L1 : g_L0) + (size_t)b*NN*NN;
    float*       Mm = (rel ? g_M1 : g_M0) + (size_t)b*NN*NN;
    int t = threadIdx.x;
    int warp = t >> 5, lane = t & 31;
    int warpM = (warp >> 1) * 32, warpN = (warp & 1) * 32;
    int g = lane >> 2, tg = lane & 3;
    int am = (t >> 3), ak = (t & 7) * 4;
    int bk = (t >> 4), bn = (t & 15) * 4;
    float4 ar[4], br[2];
    float acc[2][4][4] = {};
#pragma unroll
    for (int r = 0; r < 4; r++) ar[r] = *(const float4*)(Lm + (size_t)(am + r*32)*NN + ak);
#pragma unroll
    for (int r = 0; r < 2; r++) br[r] = *(const float4*)(Lm + (size_t)(bk + r*16)*NN + bcol + bn);
    for (int k0 = 0; k0 < NN; k0 += 32) {
#pragma unroll
        for (int r = 0; r < 4; r++) *(uint4*)&As[am + r*32][ak] = f2tf4(ar[r]);
#pragma unroll
        for (int r = 0; r < 2; r++) *(uint4*)&Bs[bk + r*16][bn] = f2tf4(br[r]);
        __syncthreads();
        if (k0 + 32 < NN) {
#pragma unroll
            for (int r = 0; r < 4; r++) ar[r] = *(const float4*)(Lm + (size_t)(am + r*32)*NN + k0 + 32 + ak);
#pragma unroll
            for (int r = 0; r < 2; r++) br[r] = *(const float4*)(Lm + (size_t)(k0 + 32 + bk + r*16)*NN + bcol + bn);
        }
#pragma unroll
        for (int ks = 0; ks < 4; ks++) {
            int kb = ks * 8;
            unsigned a[2][4], bb[4][2];
#pragma unroll
            for (int mt = 0; mt < 2; mt++) {
                int r0 = warpM + mt*16 + g;
                a[mt][0] = As[r0][kb + tg];
                a[mt][1] = As[r0 + 8][kb + tg];
                a[mt][2] = As[r0][kb + tg + 4];
                a[mt][3] = As[r0 + 8][kb + tg + 4];
            }
#pragma unroll
            for (int nt = 0; nt < 4; nt++) {
                int c0 = warpN + nt*8 + g;
                bb[nt][0] = Bs[kb + tg][c0];
                bb[nt][1] = Bs[kb + tg + 4][c0];
            }
#pragma unroll
            for (int mt = 0; mt < 2; mt++)
#pragma unroll
                for (int nt = 0; nt < 4; nt++)
                    mma_tf32(acc[mt][nt], a[mt], bb[nt]);
        }
        __syncthreads();
    }
#pragma unroll
    for (int nt = 0; nt < 4; nt++) {
        int c0 = bcol + warpN + nt*8 + tg*2;
#pragma unroll
        for (int mt = 0; mt < 2; mt++) {
            int r0 = warpM + mt*16 + g;
            Mm[(size_t)r0*NN + c0]           = 2.f*acc[mt][nt][0] - (r0 == c0 ? 1.f : 0.f);
            Mm[(size_t)r0*NN + c0 + 1]       = 2.f*acc[mt][nt][1] - (r0 == c0 + 1 ? 1.f : 0.f);
            Mm[(size_t)(r0 + 8)*NN + c0]     = 2.f*acc[mt][nt][2] - (r0 + 8 == c0 ? 1.f : 0.f);
            Mm[(size_t)(r0 + 8)*NN + c0 + 1] = 2.f*acc[mt][nt][3] - (r0 + 8 == c0 + 1 ? 1.f : 0.f);
        }
    }
}

// ====== Chebyshev terms: grid.y in {0..3} -> (rel, term); T = {L,M}[rel] @ X =====
// term==0 blocks additionally copy raw X into concat slot rel*3.
__global__ __launch_bounds__(256) void k_cheb(const float* __restrict__ X, int fin, int w) {
    __shared__ unsigned As[128][36];
    __shared__ unsigned Bs[32][68];
    int rel = blockIdx.y >> 1, term = blockIdx.y & 1;
    int b = blockIdx.z, bcol = blockIdx.x * 64;
    const float* Am = (rel ? (term ? g_M1 : g_L1) : (term ? g_M0 : g_L0)) + (size_t)b*NN*NN;
    const float* Bm = X + (size_t)b*NN*fin;
    float* Cm   = g_Xcat + (size_t)b*NN*w + (size_t)(1 + term + rel*3)*fin;
    float* Copy = term ? nullptr : g_Xcat + (size_t)b*NN*w + (size_t)(rel*3)*fin;
    int t = threadIdx.x;
    int warp = t >> 5, lane = t & 31;
    int warpM = (warp >> 1) * 32, warpN = (warp & 1) * 32;
    int g = lane >> 2, tg = lane & 3;
    int am = (t >> 3), ak = (t & 7) * 4;
    int bk = (t >> 4), bn = (t & 15) * 4;
    float4 ar[4], br[2];
    float acc[2][4][4] = {};
#pragma unroll
    for (int r = 0; r < 4; r++) ar[r] = *(const float4*)(Am + (size_t)(am + r*32)*NN + ak);
#pragma unroll
    for (int r = 0; r < 2; r++) br[r] = *(const float4*)(Bm + (size_t)(bk + r*16)*fin + bcol + bn);
    for (int k0 = 0; k0 < NN; k0 += 32) {
#pragma unroll
        for (int r = 0; r < 4; r++) *(uint4*)&As[am + r*32][ak] = f2tf4(ar[r]);
#pragma unroll
        for (int r = 0; r < 2; r++) {
            *(uint4*)&Bs[bk + r*16][bn] = f2tf4(br[r]);
            if (Copy) *(float4*)(Copy + (size_t)(k0 + bk + r*16)*w + bcol + bn) = br[r];
        }
        __syncthreads();
        if (k0 + 32 < NN) {
#pragma unroll
            for (int r = 0; r < 4; r++) ar[r] = *(const float4*)(Am + (size_t)(am + r*32)*NN + k0 + 32 + ak);
#pragma unroll
            for (int r = 0; r < 2; r++) br[r] = *(const float4*)(Bm + (size_t)(k0 + 32 + bk + r*16)*fin + bcol + bn);
        }
#pragma unroll
        for (int ks = 0; ks < 4; ks++) {
            int kb = ks * 8;
            unsigned a[2][4], bb[4][2];
#pragma unroll
            for (int mt = 0; mt < 2; mt++) {
                int r0 = warpM + mt*16 + g;
                a[mt][0] = As[r0][kb + tg];
                a[mt][1] = As[r0 + 8][kb + tg];
                a[mt][2] = As[r0][kb + tg + 4];
                a[mt][3] = As[r0 + 8][kb + tg + 4];
            }
#pragma unroll
            for (int nt = 0; nt < 4; nt++) {
                int c0 = warpN + nt*8 + g;
                bb[nt][0] = Bs[kb + tg][c0];
                bb[nt][1] = Bs[kb + tg + 4][c0];
            }
#pragma unroll
            for (int mt = 0; mt < 2; mt++)
#pragma unroll
                for (int nt = 0; nt < 4; nt++)
                    mma_tf32(acc[mt][nt], a[mt], bb[nt]);
        }
        __syncthreads();
    }
#pragma unroll
    for (int nt = 0; nt < 4; nt++) {
        int c0 = bcol + warpN + nt*8 + tg*2;
#pragma unroll
        for (int mt = 0; mt < 2; mt++) {
            int r0 = warpM + mt*16 + g;
            Cm[(size_t)r0*w + c0]           = acc[mt][nt][0];
            Cm[(size_t)r0*w + c0 + 1]       = acc[mt][nt][1];
            Cm[(size_t)(r0 + 8)*w + c0]     = acc[mt][nt][2];
            Cm[(size_t)(r0 + 8)*w + c0 + 1] = acc[mt][nt][3];
        }
    }
}

// ===== TF32 FC GEMM: O = relu(BN(mask * (Xcat @ W + bias))) ; M=4096 =====
__global__ __launch_bounds__(256) void k_fcgemm(
        const float* __restrict__ X, const float* __restrict__ W,
        const float* __restrict__ bias, const float* __restrict__ bnm,
        const float* __restrict__ bnv, const float* __restrict__ bng,
        const float* __restrict__ bnb, const float* __restrict__ mask,
        float* __restrict__ O, int K, int Nc) {
    __shared__ unsigned As[128][36];
    __shared__ unsigned Bs[32][68];
    int brow = blockIdx.y * 128;
    int bcol = blockIdx.x * 64;
    int t = threadIdx.x;
    int warp = t >> 5, lane = t & 31;
    int warpM = (warp >> 1) * 32, warpN = (warp & 1) * 32;
    int g = lane >> 2, tg = lane & 3;
    int am = (t >> 3), ak = (t & 7) * 4;
    int bk = (t >> 4), bn = (t & 15) * 4;
    float4 ar[4], br[2];
    float acc[2][4][4] = {};
#pragma unroll
    for (int r = 0; r < 4; r++) ar[r] = *(const float4*)(X + (size_t)(brow + am + r*32)*K + ak);
#pragma unroll
    for (int r = 0; r < 2; r++) br[r] = *(const float4*)(W + (size_t)(bk + r*16)*Nc + bcol + bn);
    for (int k0 = 0; k0 < K; k0 += 32) {
#pragma unroll
        for (int r = 0; r < 4; r++) *(uint4*)&As[am + r*32][ak] = f2tf4(ar[r]);
#pragma unroll
        for (int r = 0; r < 2; r++) *(uint4*)&Bs[bk + r*16][bn] = f2tf4(br[r]);
        __syncthreads();
        if (k0 + 32 < K) {
#pragma unroll
            for (int r = 0; r < 4; r++) ar[r] = *(const float4*)(X + (size_t)(brow + am + r*32)*K + k0 + 32 + ak);
#pragma unroll
            for (int r = 0; r < 2; r++) br[r] = *(const float4*)(W + (size_t)(k0 + 32 + bk + r*16)*Nc + bcol + bn);
        }
#pragma unroll
        for (int ks = 0; ks < 4; ks++) {
            int kb = ks * 8;
            unsigned a[2][4], bb[4][2];
#pragma unroll
            for (int mt = 0; mt < 2; mt++) {
                int r0 = warpM + mt*16 + g;
                a[mt][0] = As[r0][kb + tg];
                a[mt][1] = As[r0 + 8][kb + tg];
                a[mt][2] = As[r0][kb + tg + 4];
                a[mt][3] = As[r0 + 8][kb + tg + 4];
            }
#pragma unroll
            for (int nt = 0; nt < 4; nt++) {
                int c0 = warpN + nt*8 + g;
                bb[nt][0] = Bs[kb + tg][c0];
                bb[nt][1] = Bs[kb + tg + 4][c0];
            }
#pragma unroll
            for (int mt = 0; mt < 2; mt++)
#pragma unroll
                for (int nt = 0; nt < 4; nt++)
                    mma_tf32(acc[mt][nt], a[mt], bb[nt]);
        }
        __syncthreads();
    }
#pragma unroll
    for (int nt = 0; nt < 4; nt++) {
        int c0 = bcol + warpN + nt*8 + tg*2;
        float sc0 = bng[c0]     * rsqrtf(bnv[c0]     + EPS_BN);
        float sc1 = bng[c0 + 1] * rsqrtf(bnv[c0 + 1] + EPS_BN);
        float bi0 = bias[c0], bi1 = bias[c0 + 1];
        float m0 = bnm[c0], m1 = bnm[c0 + 1];
        float be0 = bnb[c0], be1 = bnb[c0 + 1];
#pragma unroll
        for (int mt = 0; mt < 2; mt++) {
            int r0 = brow + warpM + mt*16 + g;
            float mk0 = mask[r0], mk1 = mask[r0 + 8];
            float v;
            v = ((acc[mt][nt][0] + bi0)*mk0 - m0)*sc0 + be0;
            O[(size_t)r0*Nc + c0]         = fmaxf(v, 0.f);
            v = ((acc[mt][nt][1] + bi1)*mk0 - m1)*sc1 + be1;
            O[(size_t)r0*Nc + c0 + 1]     = fmaxf(v, 0.f);
            v = ((acc[mt][nt][2] + bi0)*mk1 - m0)*sc0 + be0;
            O[(size_t)(r0 + 8)*Nc + c0]     = fmaxf(v, 0.f);
            v = ((acc[mt][nt][3] + bi1)*mk1 - m1)*sc1 + be1;
            O[(size_t)(r0 + 8)*Nc + c0 + 1] = fmaxf(v, 0.f);
        }
    }
}

// ---------------- max-pool over nodes ----------------
__global__ void k_pool(const float* __restrict__ H) {
    int b = blockIdx.x, c = threadIdx.x;      // 512
    float mx = H[(size_t)(b*NN)*512 + c];
    for (int n = 1; n < NN; n++)
        mx = fmaxf(mx, H[(size_t)(b*NN + n)*512 + c]);
    g_pool[b*512 + c] = mx;
}

// ---------------- classifier ----------------
__global__ void k_fc1(const float* __restrict__ fW1, const float* __restrict__ fb1) {
    int b = blockIdx.x, t = threadIdx.x;      // 256
    __shared__ float ps[512];
    for (int i = t; i < 512; i += 256) ps[i] = g_pool[b*512 + i];
    __syncthreads();
    float acc = fb1[t];
#pragma unroll 4
    for (int k = 0; k < 512; k++) acc += ps[k] * fW1[k*NH + t];
    g_fc1[b*NH + t] = acc;
}

__global__ void k_fc2(const float* __restrict__ fW2, const float* __restrict__ fb2,
                      float* __restrict__ out) {
    int b = blockIdx.x, t = threadIdx.x;      // 32
    __shared__ float ps[NH];
    for (int i = t; i < NH; i += 32) ps[i] = g_fc1[b*NH + i];
    __syncthreads();
    if (t < OUT) {
        float acc = fb2[t];
#pragma unroll 4
        for (int k = 0; k < NH; k++) acc += ps[k] * fW2[k*OUT + t];
        out[b*OUT + t] = acc;
    }
}

// ---------------- host launch ----------------
static void* dev_ptr(const void* sym) {
    void* p = nullptr;
    cudaGetSymbolAddress(&p, sym);
    return p;
}

extern "C" void kernel_launch(void* const* d_in, const int* in_sizes, int n_in,
                              void* d_out, int out_size) {
    const float* x    = (const float*)d_in[0];
    const float* A    = (const float*)d_in[1];
    const float* mask = (const float*)d_in[2];
    const float* eW1  = (const float*)d_in[3];
    const float* eb1  = (const float*)d_in[4];
    const float* eW2  = (const float*)d_in[5];
    const float* eb2  = (const float*)d_in[6];
    const float* gW[3]  = {(const float*)d_in[7],  (const float*)d_in[13], (const float*)d_in[19]};
    const float* gb[3]  = {(const float*)d_in[8],  (const float*)d_in[14], (const float*)d_in[20]};
    const float* bng[3] = {(const float*)d_in[9],  (const float*)d_in[15], (const float*)d_in[21]};
    const float* bnb[3] = {(const float*)d_in[10], (const float*)d_in[16], (const float*)d_in[22]};
    const float* bnm[3] = {(const float*)d_in[11], (const float*)d_in[17], (const float*)d_in[23]};
    const float* bnv[3] = {(const float*)d_in[12], (const float*)d_in[18], (const float*)d_in[24]};
    const float* fW1 = (const float*)d_in[25];
    const float* fb1 = (const float*)d_in[26];
    const float* fW2 = (const float*)d_in[27];
    const float* fb2 = (const float*)d_in[28];
    float* out = (float*)d_out;

    float* p_Xcat = (float*)dev_ptr(g_Xcat);
    float* p_h0   = (float*)dev_ptr(g_h0);
    float* p_h1   = (float*)dev_ptr(g_h1);

    // edge adjacency
    k_uv<<<B*NN, HE>>>(x, eW1, eb1);
    k_score<<<B*(NN/IC), 128>>>(eW2, eb2);
    k_y<<<B*NN, NN>>>(mask);
    k_an<<<512, 256>>>();

    // Laplacians + M = 2L^2 - I (shared by all 3 layers)
    k_D2<<<2*B, NN>>>(A);
    k_L2<<<512, 256>>>(A);
    k_mgemm<<<dim3(2, 2, B), 256>>>();

    const int   FIN[3]  = {128, 64, 256};
    const int   FOUT[3] = {64, 256, 512};
    const float* Xin[3] = {x, p_h0, p_h1};
    float*      Hout[3] = {p_h0, p_h1, p_h0};

    for (int li = 0; li < 3; li++) {
        int fin = FIN[li], f = FOUT[li], w = 6*fin;
        k_cheb<<<dim3(fin/64, 4, B), 256>>>(Xin[li], fin, w);
        dim3 gf(f/64, (B*NN)/128);
        k_fcgemm<<<gf, 256>>>(p_Xcat, gW[li], gb[li], bnm[li], bnv[li],
                              bng[li], bnb[li], mask, Hout[li], w, f);
    }

    k_pool<<<B, 512>>>(p_h0);
    k_fc1<<<B, NH>>>(fW1, fb1);
    k_fc2<<<B, 32>>>(fW2, fb2, out);
}

// round 14
// speedup vs baseline: 1.3706x; 1.0830x over previous
#include <cuda_runtime.h>
#include <math.h>

#define B 32
#define NN 128
#define C 128
#define HE 64
#define NH 256
#define OUT 10
#define EPS_BN 1e-5f

// ---------------- scratch (device globals; no allocs allowed) ----------------
__device__ float g_u[B*NN*HE];
__device__ float g_v[B*NN*HE];
__device__ float g_s[B*NN*NN];
__device__ float g_L0[B*NN*NN];
__device__ float g_L1[B*NN*NN];
__device__ float g_M0[B*NN*NN];
__device__ float g_M1[B*NN*NN];
__device__ float g_Xcat[B*NN*1536];   // max 6*256 wide
__device__ float g_h0[B*NN*512];
__device__ float g_h1[B*NN*512];
__device__ float g_pool[B*512];
__device__ float g_fc1[B*NH];

__device__ __forceinline__ unsigned f2tf(float f) {
    unsigned u;
    asm("cvt.rna.tf32.f32 %0, %1;" : "=r"(u) : "f"(f));
    return u;
}
__device__ __forceinline__ uint4 f2tf4(float4 v) {
    uint4 s; s.x = f2tf(v.x); s.y = f2tf(v.y); s.z = f2tf(v.z); s.w = f2tf(v.w);
    return s;
}

__device__ __forceinline__ void mma_tf32(float c[4], const unsigned a[4], const unsigned b[2]) {
    asm volatile(
        "mma.sync.aligned.m16n8k8.row.col.f32.tf32.tf32.f32 "
        "{%0,%1,%2,%3}, {%4,%5,%6,%7}, {%8,%9}, {%0,%1,%2,%3};"
        : "+f"(c[0]), "+f"(c[1]), "+f"(c[2]), "+f"(c[3])
        : "r"(a[0]), "r"(a[1]), "r"(a[2]), "r"(a[3]), "r"(b[0]), "r"(b[1]));
}

// ---------------- edge MLP: u = x@eW1[:C]+eb1, v = x@eW1[C:] ----------------
__global__ void k_uv(const float* __restrict__ x, const float* __restrict__ eW1,
                     const float* __restrict__ eb1) {
    int row = blockIdx.x;            // b*NN + n
    __shared__ float xs[C];
    for (int c = threadIdx.x; c < C; c += blockDim.x) xs[c] = x[row*C + c];
    __syncthreads();
    int t = threadIdx.x;             // 64 threads = HE
    float u = 0.f, v = 0.f;
#pragma unroll 4
    for (int c = 0; c < C; c++) {
        float xv = xs[c];
        u += xv * eW1[c*HE + t];
        v += xv * eW1[(C + c)*HE + t];
    }
    g_u[row*HE + t] = u + eb1[t];
    g_v[row*HE + t] = v;
}

// ---------------- edge scores s[b,i,j] ----------------
#define IC 16
__global__ void k_score(const float* __restrict__ eW2, const float* __restrict__ eb2) {
    int b  = blockIdx.x / (NN / IC);
    int i0 = (blockIdx.x % (NN / IC)) * IC;
    __shared__ float vs[NN*(HE + 1)];
    __shared__ float us[IC*HE];
    __shared__ float w2[HE];
    int tid = threadIdx.x;           // 128
    for (int idx = tid; idx < NN*HE; idx += 128) {
        int j = idx / HE, h = idx % HE;
        vs[j*(HE + 1) + h] = g_v[(b*NN + j)*HE + h];
    }
    for (int idx = tid; idx < IC*HE; idx += 128)
        us[idx] = g_u[(b*NN + i0)*HE + idx];
    if (tid < HE) w2[tid] = eW2[tid];
    __syncthreads();
    float e2 = eb2[0];
    int j = tid;
    for (int ii = 0; ii < IC; ii++) {
        float acc = e2;
#pragma unroll 8
        for (int h = 0; h < HE; h++) {
            float t = us[ii*HE + h] + vs[j*(HE + 1) + h];
            acc += w2[h] * fmaxf(t, 0.f);
        }
        g_s[(b*NN + i0 + ii)*NN + j] = acc;
    }
}

// ====== fused adjacency: blocks 0..31 -> L0 from A; 32..63 -> L1 from s ======
// rel1 exploits: An_ij = An_ji = y_ij / rs_i for i<j (y strictly upper-tri).
__global__ void k_adj(const float* __restrict__ A, const float* __restrict__ mask,
                      float* __restrict__ L0, float* __restrict__ L1) {
    extern __shared__ float sy[];                 // [128][129]
    __shared__ float rs[NN];
    __shared__ float Ds[NN];
    __shared__ float mrow[NN];
    int v = blockIdx.x;
    int rel = v >> 5, b = v & 31;
    int t = threadIdx.x;                          // 256
    if (rel == 0) {
        const float* Am = A + (size_t)b*NN*NN;
        if (t < NN) {
            float s = 0.f;
#pragma unroll 4
            for (int i = 0; i < NN; i++) s += Am[i*NN + t];
            Ds[t] = rsqrtf(s + 1e-5f);
        }
        __syncthreads();
        float* Lm = L0 + (size_t)b*NN*NN;
        for (int idx = t; idx < NN*NN; idx += 256) {
            int i = idx >> 7, j = idx & 127;
            Lm[idx] = Ds[i] * Am[idx] * Ds[j];
        }
        return;
    }
    // ---- rel 1 ----
    const float* sm = g_s + (size_t)b*NN*NN;
    for (int idx = t; idx < NN*NN; idx += 256)
        sy[(idx >> 7)*129 + (idx & 127)] = sm[idx];
    if (t < NN) mrow[t] = mask[b*NN + t];
    __syncthreads();
    // y (upper-tri), zero lower+diag
    for (int idx = t; idx < NN*NN; idx += 256) {
        int i = idx >> 7, j = idx & 127;
        if (i < j) {
            float m = mrow[i] * mrow[j];
            float yv = 0.f;
            if (m != 0.f)
                yv = expf(0.5f * (sy[i*129 + j] + sy[j*129 + i]));
            sy[i*129 + j] = yv;
            sy[j*129 + i] = 0.f;
        } else if (i == j) {
            sy[i*129 + i] = 0.f;
        }
    }
    __syncthreads();
    // row sums
    if (t < NN) {
        float s = 0.f;
#pragma unroll 4
        for (int j = 0; j < NN; j++) s += sy[t*129 + j];
        rs[t] = (s == 0.f) ? 1.f : s;
    }
    __syncthreads();
    // symmetric An in place
    for (int idx = t; idx < NN*NN; idx += 256) {
        int i = idx >> 7, j = idx & 127;
        if (i < j) {
            float an = sy[i*129 + j] / rs[i];
            sy[i*129 + j] = an;
            sy[j*129 + i] = an;
        }
    }
    __syncthreads();
    // column sums -> D
    if (t < NN) {
        float s = 0.f;
#pragma unroll 4
        for (int i = 0; i < NN; i++) s += sy[i*129 + t];
        Ds[t] = rsqrtf(s + 1e-5f);
    }
    __syncthreads();
    float* Lm = L1 + (size_t)b*NN*NN;
    for (int idx = t; idx < NN*NN; idx += 256) {
        int i = idx >> 7, j = idx & 127;
        Lm[idx] = Ds[i] * sy[i*129 + j] * Ds[j];
    }
}

// =============== GEMM config ===============
template<int NT> struct Cfg {
    static constexpr int WN = NT / 32;        // warps along N
    static constexpr int WM = 8 / WN;         // warps along M
    static constexpr int ROWS = 128 / WM;     // rows per warp
    static constexpr int MT = ROWS / 16;      // m16 tiles per warp
    static constexpr int TPR = NT / 4;        // threads per B row
    static constexpr int RSTEP = 256 / TPR;   // B rows per iteration
    static constexpr int IB = 32 / RSTEP;     // B load iterations
};

// =============== M = 2*L@L - I  (tf32 MMA, 128x128 tile) =======
__global__ __launch_bounds__(256) void k_mgemm() {
    typedef Cfg<128> G;
    __shared__ unsigned As[128][36];
    __shared__ unsigned Bs[32][132];
    int rel = blockIdx.y, b = blockIdx.z, bcol = 0;
    const float* Lm = (rel ? g_L1 : g_L0) + (size_t)b*NN*NN;
    float*       Mm = (rel ? g_M1 : g_M0) + (size_t)b*NN*NN;
    int t = threadIdx.x;
    int warp = t >> 5, lane = t & 31;
    int warpM = (warp / G::WN) * G::ROWS, warpN = (warp % G::WN) * 32;
    int g = lane >> 2, tg = lane & 3;
    int am = (t >> 3), ak = (t & 7) * 4;
    int bk = t / G::TPR, bn = (t % G::TPR) * 4;
    float4 ar[4], br[G::IB];
    float acc[G::MT][4][4] = {};
#pragma unroll
    for (int r = 0; r < 4; r++) ar[r] = *(const float4*)(Lm + (size_t)(am + r*32)*NN + ak);
#pragma unroll
    for (int r = 0; r < G::IB; r++) br[r] = *(const float4*)(Lm + (size_t)(bk + r*G::RSTEP)*NN + bcol + bn);
    for (int k0 = 0; k0 < NN; k0 += 32) {
#pragma unroll
        for (int r = 0; r < 4; r++) *(uint4*)&As[am + r*32][ak] = f2tf4(ar[r]);
#pragma unroll
        for (int r = 0; r < G::IB; r++) *(uint4*)&Bs[bk + r*G::RSTEP][bn] = f2tf4(br[r]);
        __syncthreads();
        if (k0 + 32 < NN) {
#pragma unroll
            for (int r = 0; r < 4; r++) ar[r] = *(const float4*)(Lm + (size_t)(am + r*32)*NN + k0 + 32 + ak);
#pragma unroll
            for (int r = 0; r < G::IB; r++) br[r] = *(const float4*)(Lm + (size_t)(k0 + 32 + bk + r*G::RSTEP)*NN + bcol + bn);
        }
#pragma unroll
        for (int ks = 0; ks < 4; ks++) {
            int kb = ks * 8;
            unsigned a[G::MT][4], bb[4][2];
#pragma unroll
            for (int mt = 0; mt < G::MT; mt++) {
                int r0 = warpM + mt*16 + g;
                a[mt][0] = As[r0][kb + tg];
                a[mt][1] = As[r0 + 8][kb + tg];
                a[mt][2] = As[r0][kb + tg + 4];
                a[mt][3] = As[r0 + 8][kb + tg + 4];
            }
#pragma unroll
            for (int nt = 0; nt < 4; nt++) {
                int c0 = warpN + nt*8 + g;
                bb[nt][0] = Bs[kb + tg][c0];
                bb[nt][1] = Bs[kb + tg + 4][c0];
            }
#pragma unroll
            for (int mt = 0; mt < G::MT; mt++)
#pragma unroll
                for (int nt = 0; nt < 4; nt++)
                    mma_tf32(acc[mt][nt], a[mt], bb[nt]);
        }
        __syncthreads();
    }
#pragma unroll
    for (int nt = 0; nt < 4; nt++) {
        int c0 = bcol + warpN + nt*8 + tg*2;
#pragma unroll
        for (int mt = 0; mt < G::MT; mt++) {
            int r0 = warpM + mt*16 + g;
            Mm[(size_t)r0*NN + c0]           = 2.f*acc[mt][nt][0] - (r0 == c0 ? 1.f : 0.f);
            Mm[(size_t)r0*NN + c0 + 1]       = 2.f*acc[mt][nt][1] - (r0 == c0 + 1 ? 1.f : 0.f);
            Mm[(size_t)(r0 + 8)*NN + c0]     = 2.f*acc[mt][nt][2] - (r0 + 8 == c0 ? 1.f : 0.f);
            Mm[(size_t)(r0 + 8)*NN + c0 + 1] = 2.f*acc[mt][nt][3] - (r0 + 8 == c0 + 1 ? 1.f : 0.f);
        }
    }
}

// ====== Chebyshev terms: grid.y in {0..3} -> (rel, term); T = {L,M}[rel] @ X =====
template<int NT>
__global__ __launch_bounds__(256) void k_cheb(const float* __restrict__ X, int fin, int w) {
    typedef Cfg<NT> G;
    __shared__ unsigned As[128][36];
    __shared__ unsigned Bs[32][NT + 4];
    int rel = blockIdx.y >> 1, term = blockIdx.y & 1;
    int b = blockIdx.z, bcol = blockIdx.x * NT;
    const float* Am = (rel ? (term ? g_M1 : g_L1) : (term ? g_M0 : g_L0)) + (size_t)b*NN*NN;
    const float* Bm = X + (size_t)b*NN*fin;
    float* Cm   = g_Xcat + (size_t)b*NN*w + (size_t)(1 + term + rel*3)*fin;
    float* Copy = term ? nullptr : g_Xcat + (size_t)b*NN*w + (size_t)(rel*3)*fin;
    int t = threadIdx.x;
    int warp = t >> 5, lane = t & 31;
    int warpM = (warp / G::WN) * G::ROWS, warpN = (warp % G::WN) * 32;
    int g = lane >> 2, tg = lane & 3;
    int am = (t >> 3), ak = (t & 7) * 4;
    int bk = t / G::TPR, bn = (t % G::TPR) * 4;
    float4 ar[4], br[G::IB];
    float acc[G::MT][4][4] = {};
#pragma unroll
    for (int r = 0; r < 4; r++) ar[r] = *(const float4*)(Am + (size_t)(am + r*32)*NN + ak);
#pragma unroll
    for (int r = 0; r < G::IB; r++) br[r] = *(const float4*)(Bm + (size_t)(bk + r*G::RSTEP)*fin + bcol + bn);
    for (int k0 = 0; k0 < NN; k0 += 32) {
#pragma unroll
        for (int r = 0; r < 4; r++) *(uint4*)&As[am + r*32][ak] = f2tf4(ar[r]);
#pragma unroll
        for (int r = 0; r < G::IB; r++) {
            *(uint4*)&Bs[bk + r*G::RSTEP][bn] = f2tf4(br[r]);
            if (Copy) *(float4*)(Copy + (size_t)(k0 + bk + r*G::RSTEP)*w + bcol + bn) = br[r];
        }
        __syncthreads();
        if (k0 + 32 < NN) {
#pragma unroll
            for (int r = 0; r < 4; r++) ar[r] = *(const float4*)(Am + (size_t)(am + r*32)*NN + k0 + 32 + ak);
#pragma unroll
            for (int r = 0; r < G::IB; r++) br[r] = *(const float4*)(Bm + (size_t)(k0 + 32 + bk + r*G::RSTEP)*fin + bcol + bn);
        }
#pragma unroll
        for (int ks = 0; ks < 4; ks++) {
            int kb = ks * 8;
            unsigned a[G::MT][4], bb[4][2];
#pragma unroll
            for (int mt = 0; mt < G::MT; mt++) {
                int r0 = warpM + mt*16 + g;
                a[mt][0] = As[r0][kb + tg];
                a[mt][1] = As[r0 + 8][kb + tg];
                a[mt][2] = As[r0][kb + tg + 4];
                a[mt][3] = As[r0 + 8][kb + tg + 4];
            }
#pragma unroll
            for (int nt = 0; nt < 4; nt++) {
                int c0 = warpN + nt*8 + g;
                bb[nt][0] = Bs[kb + tg][c0];
                bb[nt][1] = Bs[kb + tg + 4][c0];
            }
#pragma unroll
            for (int mt = 0; mt < G::MT; mt++)
#pragma unroll
                for (int nt = 0; nt < 4; nt++)
                    mma_tf32(acc[mt][nt], a[mt], bb[nt]);
        }
        __syncthreads();
    }
#pragma unroll
    for (int nt = 0; nt < 4; nt++) {
        int c0 = bcol + warpN + nt*8 + tg*2;
#pragma unroll
        for (int mt = 0; mt < G::MT; mt++) {
            int r0 = warpM + mt*16 + g;
            Cm[(size_t)r0*w + c0]           = acc[mt][nt][0];
            Cm[(size_t)r0*w + c0 + 1]       = acc[mt][nt][1];
            Cm[(size_t)(r0 + 8)*w + c0]     = acc[mt][nt][2];
            Cm[(size_t)(r0 + 8)*w + c0 + 1] = acc[mt][nt][3];
        }
    }
}

// ===== TF32 FC GEMM: O = relu(BN(mask * (Xcat @ W + bias))) ; M=4096 =====
template<int NT>
__global__ __launch_bounds__(256) void k_fcgemm(
        const float* __restrict__ X, const float* __restrict__ W,
        const float* __restrict__ bias, const float* __restrict__ bnm,
        const float* __restrict__ bnv, const float* __restrict__ bng,
        const float* __restrict__ bnb, const float* __restrict__ mask,
        float* __restrict__ O, int K, int Nc) {
    typedef Cfg<NT> G;
    __shared__ unsigned As[128][36];
    __shared__ unsigned Bs[32][NT + 4];
    int brow = blockIdx.y * 128;
    int bcol = blockIdx.x * NT;
    int t = threadIdx.x;
    int warp = t >> 5, lane = t & 31;
    int warpM = (warp / G::WN) * G::ROWS, warpN = (warp % G::WN) * 32;
    int g = lane >> 2, tg = lane & 3;
    int am = (t >> 3), ak = (t & 7) * 4;
    int bk = t / G::TPR, bn = (t % G::TPR) * 4;
    float4 ar[4], br[G::IB];
    float acc[G::MT][4][4] = {};
#pragma unroll
    for (int r = 0; r < 4; r++) ar[r] = *(const float4*)(X + (size_t)(brow + am + r*32)*K + ak);
#pragma unroll
    for (int r = 0; r < G::IB; r++) br[r] = *(const float4*)(W + (size_t)(bk + r*G::RSTEP)*Nc + bcol + bn);
    for (int k0 = 0; k0 < K; k0 += 32) {
#pragma unroll
        for (int r = 0; r < 4; r++) *(uint4*)&As[am + r*32][ak] = f2tf4(ar[r]);
#pragma unroll
        for (int r = 0; r < G::IB; r++) *(uint4*)&Bs[bk + r*G::RSTEP][bn] = f2tf4(br[r]);
        __syncthreads();
        if (k0 + 32 < K) {
#pragma unroll
            for (int r = 0; r < 4; r++) ar[r] = *(const float4*)(X + (size_t)(brow + am + r*32)*K + k0 + 32 + ak);
#pragma unroll
            for (int r = 0; r < G::IB; r++) br[r] = *(const float4*)(W + (size_t)(k0 + 32 + bk + r*G::RSTEP)*Nc + bcol + bn);
        }
#pragma unroll
        for (int ks = 0; ks < 4; ks++) {
            int kb = ks * 8;
            unsigned a[G::MT][4], bb[4][2];
#pragma unroll
            for (int mt = 0; mt < G::MT; mt++) {
                int r0 = warpM + mt*16 + g;
                a[mt][0] = As[r0][kb + tg];
                a[mt][1] = As[r0 + 8][kb + tg];
                a[mt][2] = As[r0][kb + tg + 4];
                a[mt][3] = As[r0 + 8][kb + tg + 4];
            }
#pragma unroll
            for (int nt = 0; nt < 4; nt++) {
                int c0 = warpN + nt*8 + g;
                bb[nt][0] = Bs[kb + tg][c0];
                bb[nt][1] = Bs[kb + tg + 4][c0];
            }
#pragma unroll
            for (int mt = 0; mt < G::MT; mt++)
#pragma unroll
                for (int nt = 0; nt < 4; nt++)
                    mma_tf32(acc[mt][nt], a[mt], bb[nt]);
        }
        __syncthreads();
    }
#pragma unroll
    for (int nt = 0; nt < 4; nt++) {
        int c0 = bcol + warpN + nt*8 + tg*2;
        float sc0 = bng[c0]     * rsqrtf(bnv[c0]     + EPS_BN);
        float sc1 = bng[c0 + 1] * rsqrtf(bnv[c0 + 1] + EPS_BN);
        float bi0 = bias[c0], bi1 = bias[c0 + 1];
        float m0 = bnm[c0], m1 = bnm[c0 + 1];
        float be0 = bnb[c0], be1 = bnb[c0 + 1];
#pragma unroll
        for (int mt = 0; mt < G::MT; mt++) {
            int r0 = brow + warpM + mt*16 + g;
            float mk0 = mask[r0], mk1 = mask[r0 + 8];
            float v;
            v = ((acc[mt][nt][0] + bi0)*mk0 - m0)*sc0 + be0;
            O[(size_t)r0*Nc + c0]         = fmaxf(v, 0.f);
            v = ((acc[mt][nt][1] + bi1)*mk0 - m1)*sc1 + be1;
            O[(size_t)r0*Nc + c0 + 1]     = fmaxf(v, 0.f);
            v = ((acc[mt][nt][2] + bi0)*mk1 - m0)*sc0 + be0;
            O[(size_t)(r0 + 8)*Nc + c0]     = fmaxf(v, 0.f);
            v = ((acc[mt][nt][3] + bi1)*mk1 - m1)*sc1 + be1;
            O[(size_t)(r0 + 8)*Nc + c0 + 1] = fmaxf(v, 0.f);
        }
    }
}

// ---------------- max-pool over nodes (4 independent chains) ----------------
__global__ void k_pool(const float* __restrict__ H) {
    int b = blockIdx.x, c = threadIdx.x;      // 512
    const float* Hb = H + (size_t)b*NN*512 + c;
    float m0 = Hb[0*512], m1 = Hb[1*512], m2 = Hb[2*512], m3 = Hb[3*512];
#pragma unroll 4
    for (int n = 4; n < NN; n += 4) {
        m0 = fmaxf(m0, Hb[(size_t)n*512]);
        m1 = fmaxf(m1, Hb[(size_t)(n + 1)*512]);
        m2 = fmaxf(m2, Hb[(size_t)(n + 2)*512]);
        m3 = fmaxf(m3, Hb[(size_t)(n + 3)*512]);
    }
    g_pool[b*512 + c] = fmaxf(fmaxf(m0, m1), fmaxf(m2, m3));
}

// ---------------- classifier ----------------
__global__ void k_fc1(const float* __restrict__ fW1, const float* __restrict__ fb1) {
    int b = blockIdx.x, t = threadIdx.x;      // 256
    __shared__ float ps[512];
    for (int i = t; i < 512; i += 256) ps[i] = g_pool[b*512 + i];
    __syncthreads();
    float acc = fb1[t];
#pragma unroll 4
    for (int k = 0; k < 512; k++) acc += ps[k] * fW1[k*NH + t];
    g_fc1[b*NH + t] = acc;
}

__global__ void k_fc2(const float* __restrict__ fW2, const float* __restrict__ fb2,
                      float* __restrict__ out) {
    int b = blockIdx.x, t = threadIdx.x;      // 32
    __shared__ float ps[NH];
    for (int i = t; i < NH; i += 32) ps[i] = g_fc1[b*NH + i];
    __syncthreads();
    if (t < OUT) {
        float acc = fb2[t];
#pragma unroll 4
        for (int k = 0; k < NH; k++) acc += ps[k] * fW2[k*OUT + t];
        out[b*OUT + t] = acc;
    }
}

// ---------------- host launch ----------------
static void* dev_ptr(const void* sym) {
    void* p = nullptr;
    cudaGetSymbolAddress(&p, sym);
    return p;
}

extern "C" void kernel_launch(void* const* d_in, const int* in_sizes, int n_in,
                              void* d_out, int out_size) {
    const float* x    = (const float*)d_in[0];
    const float* A    = (const float*)d_in[1];
    const float* mask = (const float*)d_in[2];
    const float* eW1  = (const float*)d_in[3];
    const float* eb1  = (const float*)d_in[4];
    const float* eW2  = (const float*)d_in[5];
    const float* eb2  = (const float*)d_in[6];
    const float* gW[3]  = {(const float*)d_in[7],  (const float*)d_in[13], (const float*)d_in[19]};
    const float* gb[3]  = {(const float*)d_in[8],  (const float*)d_in[14], (const float*)d_in[20]};
    const float* bng[3] = {(const float*)d_in[9],  (const float*)d_in[15], (const float*)d_in[21]};
    const float* bnb[3] = {(const float*)d_in[10], (const float*)d_in[16], (const float*)d_in[22]};
    const float* bnm[3] = {(const float*)d_in[11], (const float*)d_in[17], (const float*)d_in[23]};
    const float* bnv[3] = {(const float*)d_in[12], (const float*)d_in[18], (const float*)d_in[24]};
    const float* fW1 = (const float*)d_in[25];
    const float* fb1 = (const float*)d_in[26];
    const float* fW2 = (const float*)d_in[27];
    const float* fb2 = (const float*)d_in[28];
    float* out = (float*)d_out;

    float* p_Xcat = (float*)dev_ptr(g_Xcat);
    float* p_h0   = (float*)dev_ptr(g_h0);
    float* p_h1   = (float*)dev_ptr(g_h1);
    float* p_L0   = (float*)dev_ptr(g_L0);
    float* p_L1   = (float*)dev_ptr(g_L1);

    // edge adjacency (fused)
    k_uv<<<B*NN, HE>>>(x, eW1, eb1);
    k_score<<<B*(NN/IC), 128>>>(eW2, eb2);
    const int adjSmem = 128*129*4;
    cudaFuncSetAttribute(k_adj, cudaFuncAttributeMaxDynamicSharedMemorySize, adjSmem);
    k_adj<<<2*B, 256, adjSmem>>>(A, mask, p_L0, p_L1);

    // M = 2L^2 - I (shared by all 3 layers)
    k_mgemm<<<dim3(1, 2, B), 256>>>();

    const int   FIN[3]  = {128, 64, 256};
    const int   FOUT[3] = {64, 256, 512};
    const float* Xin[3] = {x, p_h0, p_h1};
    float*      Hout[3] = {p_h0, p_h1, p_h0};

    for (int li = 0; li < 3; li++) {
        int fin = FIN[li], f = FOUT[li], w = 6*fin;
        if (fin >= 128)
            k_cheb<128><<<dim3(fin/128, 4, B), 256>>>(Xin[li], fin, w);
        else
            k_cheb<64><<<dim3(fin/64, 4, B), 256>>>(Xin[li], fin, w);
        dim3 gf128(f/128, (B*NN)/128);
        dim3 gf64(f/64, (B*NN)/128);
        if (f >= 128)
            k_fcgemm<128><<<gf128, 256>>>(p_Xcat, gW[li], gb[li], bnm[li], bnv[li],
                                          bng[li], bnb[li], mask, Hout[li], w, f);
        else
            k_fcgemm<64><<<gf64, 256>>>(p_Xcat, gW[li], gb[li], bnm[li], bnv[li],
                                        bng[li], bnb[li], mask, Hout[li], w, f);
    }

    k_pool<<<B, 512>>>(p_h0);
    k_fc1<<<B, NH>>>(fW1, fb1);
    k_fc2<<<B, 32>>>(fW2, fb2, out);
}